// round 3
// baseline (speedup 1.0000x reference)
#include <cuda_runtime.h>

// Problem constants
#define BROWS 16384
#define DIN   512
#define NSP   26
#define EMB   128
#define OUTD  512
#define NI    27
#define NTRI  378          // NI*(NI+1)/2
#define KTOT  890          // DIN + NTRI
#define ZSTR  384          // padded Ztri row stride (floats)
#define WOP   896          // padded Wo row stride (floats)

// Scratch (device globals — no runtime allocation allowed)
__device__ float g_proj[BROWS * EMB];            // dense @ Wp^T + bp
__device__ float g_ztri[BROWS * ZSTR];           // lower-tri Z, padded
__device__ float g_wop [OUTD * WOP];             // Wo padded to 896, zeros past 890

// ---------------------------------------------------------------------------
// Kernel 0: pack Wo [512,890] -> g_wop [512,896] (zero padded), 16B-aligned rows
// ---------------------------------------------------------------------------
__global__ void pack_wo_kernel(const float* __restrict__ Wo) {
    int n = blockIdx.x;
    for (int k = threadIdx.x; k < WOP; k += blockDim.x) {
        g_wop[n * WOP + k] = (k < KTOT) ? Wo[(size_t)n * KTOT + k] : 0.0f;
    }
}

// ---------------------------------------------------------------------------
// Kernel 1: g_proj[B,128] = dense[B,512] @ Wp[128,512]^T + bp
// Tiled SGEMM: BM=128, BN=128, BK=16, 256 threads, 8x8 per thread
// ---------------------------------------------------------------------------
__global__ __launch_bounds__(256, 2)
void gemm_proj_kernel(const float* __restrict__ A,     // [BROWS, 512]
                      const float* __restrict__ W,     // [128, 512]
                      const float* __restrict__ bias)  // [128]
{
    __shared__ float As[16][128];
    __shared__ float Bs[16][128];

    const int tid = threadIdx.x;
    const int m0  = blockIdx.y * 128;
    const int n0  = blockIdx.x * 128;   // always 0 here (N=128)
    const int tr  = tid / 16;
    const int tc  = tid % 16;
    const int fr  = tid >> 1;           // 0..127 fill row
    const int fk  = (tid & 1) * 8;      // 0 or 8

    float acc[8][8];
#pragma unroll
    for (int i = 0; i < 8; i++)
#pragma unroll
        for (int j = 0; j < 8; j++) acc[i][j] = 0.0f;

    for (int k0 = 0; k0 < 512; k0 += 16) {
        const float4* pa = (const float4*)(A + (size_t)(m0 + fr) * 512 + k0 + fk);
        float4 a0 = pa[0], a1 = pa[1];
        const float4* pw = (const float4*)(W + (size_t)(n0 + fr) * 512 + k0 + fk);
        float4 w0 = pw[0], w1 = pw[1];

        As[fk + 0][fr] = a0.x; As[fk + 1][fr] = a0.y; As[fk + 2][fr] = a0.z; As[fk + 3][fr] = a0.w;
        As[fk + 4][fr] = a1.x; As[fk + 5][fr] = a1.y; As[fk + 6][fr] = a1.z; As[fk + 7][fr] = a1.w;
        Bs[fk + 0][fr] = w0.x; Bs[fk + 1][fr] = w0.y; Bs[fk + 2][fr] = w0.z; Bs[fk + 3][fr] = w0.w;
        Bs[fk + 4][fr] = w1.x; Bs[fk + 5][fr] = w1.y; Bs[fk + 6][fr] = w1.z; Bs[fk + 7][fr] = w1.w;
        __syncthreads();

#pragma unroll
        for (int kk = 0; kk < 16; kk++) {
            float4 av0 = *(const float4*)&As[kk][tr * 4];
            float4 av1 = *(const float4*)&As[kk][tr * 4 + 64];
            float4 bv0 = *(const float4*)&Bs[kk][tc * 4];
            float4 bv1 = *(const float4*)&Bs[kk][tc * 4 + 64];
            float a[8] = {av0.x, av0.y, av0.z, av0.w, av1.x, av1.y, av1.z, av1.w};
            float b[8] = {bv0.x, bv0.y, bv0.z, bv0.w, bv1.x, bv1.y, bv1.z, bv1.w};
#pragma unroll
            for (int i = 0; i < 8; i++)
#pragma unroll
                for (int j = 0; j < 8; j++) acc[i][j] += a[i] * b[j];
        }
        __syncthreads();
    }

    float4 bl = *(const float4*)&bias[n0 + tc * 4];
    float4 bh = *(const float4*)&bias[n0 + tc * 4 + 64];
#pragma unroll
    for (int i = 0; i < 8; i++) {
        int m = m0 + ((i < 4) ? (tr * 4 + i) : (64 + tr * 4 + (i - 4)));
        float4 v;
        v.x = acc[i][0] + bl.x; v.y = acc[i][1] + bl.y;
        v.z = acc[i][2] + bl.z; v.w = acc[i][3] + bl.w;
        *(float4*)&g_proj[(size_t)m * 128 + n0 + tc * 4] = v;
        v.x = acc[i][4] + bh.x; v.y = acc[i][5] + bh.y;
        v.z = acc[i][6] + bh.z; v.w = acc[i][7] + bh.w;
        *(float4*)&g_proj[(size_t)m * 128 + n0 + tc * 4 + 64] = v;
    }
}

// ---------------------------------------------------------------------------
// Kernel 2: per-row Z = T T^T lower-tri, T = [proj_row; sparse_row] (27x128)
// 1 warp per batch row, 2 rows per CTA. T stored transposed in smem:
// Tt[e][i], row stride 28 floats (16B-aligned float4 reads of 4 i-values).
// Each active lane (28 of 32) owns one 4x4 (i-tile, j-tile) block.
// ---------------------------------------------------------------------------
__global__ __launch_bounds__(64)
void zflat_kernel(const float* __restrict__ sparse)  // [BROWS, 26, 128]
{
    __shared__ __align__(16) float Tt[2][128 * 28];

    const int w    = threadIdx.x >> 5;
    const int lane = threadIdx.x & 31;
    const size_t b = (size_t)blockIdx.x * 2 + w;
    float* T = Tt[w];

    // fill transposed: Tt[e][0] = proj, Tt[e][1..26] = sparse rows
    {
        const float* src = g_proj + b * 128;
#pragma unroll
        for (int c = 0; c < 4; c++) {
            int e = lane + 32 * c;
            T[e * 28 + 0] = src[e];
        }
    }
    for (int i = 1; i < NI; i++) {
        const float* src = sparse + (b * NSP + (i - 1)) * 128;
#pragma unroll
        for (int c = 0; c < 4; c++) {
            int e = lane + 32 * c;
            T[e * 28 + i] = src[e];
        }
    }
    __syncwarp();

    if (lane < 28) {
        // lane -> (ti, tj), ti >= tj, row-major lower-tri order over 7x7 tiles
        int ti = 0, rem = lane;
        while (rem > ti) { rem -= (ti + 1); ti++; }
        int tj = rem;

        float acc[4][4];
#pragma unroll
        for (int r = 0; r < 4; r++)
#pragma unroll
            for (int c = 0; c < 4; c++) acc[r][c] = 0.0f;

#pragma unroll 4
        for (int e = 0; e < 128; e++) {
            float4 av = *(const float4*)&T[e * 28 + 4 * ti];
            float4 bv = *(const float4*)&T[e * 28 + 4 * tj];
            float a[4] = {av.x, av.y, av.z, av.w};
            float c4[4] = {bv.x, bv.y, bv.z, bv.w};
#pragma unroll
            for (int r = 0; r < 4; r++)
#pragma unroll
                for (int c = 0; c < 4; c++) acc[r][c] += a[r] * c4[c];
        }

        float* out = g_ztri + b * ZSTR;
#pragma unroll
        for (int r = 0; r < 4; r++) {
            int i = 4 * ti + r;
            if (i < NI) {
#pragma unroll
                for (int c = 0; c < 4; c++) {
                    int j = 4 * tj + c;
                    if (j <= i) out[i * (i + 1) / 2 + j] = acc[r][c];
                }
            }
        }
    }
}

// ---------------------------------------------------------------------------
// Kernel 3: out[B,512] = [dense | Ztri][B,890] @ Wo[512,890]^T + bo
// Virtual A: k<512 -> dense, 512<=k<890 -> g_ztri. K padded to 896.
// Each 16-wide K-tile is entirely in one source (512 is 16-aligned).
// ---------------------------------------------------------------------------
__global__ __launch_bounds__(256, 2)
void gemm_out_kernel(const float* __restrict__ dense,  // [BROWS, 512]
                     const float* __restrict__ bias,   // [512]
                     float* __restrict__ C)            // [BROWS, 512]
{
    __shared__ float As[16][128];
    __shared__ float Bs[16][128];

    const int tid = threadIdx.x;
    const int m0  = blockIdx.y * 128;
    const int n0  = blockIdx.x * 128;
    const int tr  = tid / 16;
    const int tc  = tid % 16;
    const int fr  = tid >> 1;
    const int fk  = (tid & 1) * 8;

    float acc[8][8];
#pragma unroll
    for (int i = 0; i < 8; i++)
#pragma unroll
        for (int j = 0; j < 8; j++) acc[i][j] = 0.0f;

    for (int k0 = 0; k0 < WOP; k0 += 16) {
        // ---- A fill (two-source virtual matrix) ----
        float4 a0, a1;
        if (k0 < 512) {
            const float4* p = (const float4*)(dense + (size_t)(m0 + fr) * 512 + k0 + fk);
            a0 = p[0]; a1 = p[1];
        } else if (k0 < 880) {
            const float4* p = (const float4*)(g_ztri + (size_t)(m0 + fr) * ZSTR + (k0 - 512) + fk);
            a0 = p[0]; a1 = p[1];
        } else { // last tile: k in [880, 896), valid kz < 378
            const float* p = g_ztri + (size_t)(m0 + fr) * ZSTR;
            float t[8];
#pragma unroll
            for (int j = 0; j < 8; j++) {
                int kz = (k0 - 512) + fk + j;
                t[j] = (kz < NTRI) ? p[kz] : 0.0f;
            }
            a0.x = t[0]; a0.y = t[1]; a0.z = t[2]; a0.w = t[3];
            a1.x = t[4]; a1.y = t[5]; a1.z = t[6]; a1.w = t[7];
        }
        // ---- W fill (pre-padded, always aligned & in range) ----
        const float4* pw = (const float4*)(g_wop + (size_t)(n0 + fr) * WOP + k0 + fk);
        float4 w0 = pw[0], w1 = pw[1];

        As[fk + 0][fr] = a0.x; As[fk + 1][fr] = a0.y; As[fk + 2][fr] = a0.z; As[fk + 3][fr] = a0.w;
        As[fk + 4][fr] = a1.x; As[fk + 5][fr] = a1.y; As[fk + 6][fr] = a1.z; As[fk + 7][fr] = a1.w;
        Bs[fk + 0][fr] = w0.x; Bs[fk + 1][fr] = w0.y; Bs[fk + 2][fr] = w0.z; Bs[fk + 3][fr] = w0.w;
        Bs[fk + 4][fr] = w1.x; Bs[fk + 5][fr] = w1.y; Bs[fk + 6][fr] = w1.z; Bs[fk + 7][fr] = w1.w;
        __syncthreads();

#pragma unroll
        for (int kk = 0; kk < 16; kk++) {
            float4 av0 = *(const float4*)&As[kk][tr * 4];
            float4 av1 = *(const float4*)&As[kk][tr * 4 + 64];
            float4 bv0 = *(const float4*)&Bs[kk][tc * 4];
            float4 bv1 = *(const float4*)&Bs[kk][tc * 4 + 64];
            float a[8] = {av0.x, av0.y, av0.z, av0.w, av1.x, av1.y, av1.z, av1.w};
            float b[8] = {bv0.x, bv0.y, bv0.z, bv0.w, bv1.x, bv1.y, bv1.z, bv1.w};
#pragma unroll
            for (int i = 0; i < 8; i++)
#pragma unroll
                for (int j = 0; j < 8; j++) acc[i][j] += a[i] * b[j];
        }
        __syncthreads();
    }

    float4 bl = *(const float4*)&bias[n0 + tc * 4];
    float4 bh = *(const float4*)&bias[n0 + tc * 4 + 64];
#pragma unroll
    for (int i = 0; i < 8; i++) {
        int m = m0 + ((i < 4) ? (tr * 4 + i) : (64 + tr * 4 + (i - 4)));
        float4 v;
        v.x = acc[i][0] + bl.x; v.y = acc[i][1] + bl.y;
        v.z = acc[i][2] + bl.z; v.w = acc[i][3] + bl.w;
        *(float4*)&C[(size_t)m * OUTD + n0 + tc * 4] = v;
        v.x = acc[i][4] + bh.x; v.y = acc[i][5] + bh.y;
        v.z = acc[i][6] + bh.z; v.w = acc[i][7] + bh.w;
        *(float4*)&C[(size_t)m * OUTD + n0 + tc * 4 + 64] = v;
    }
}

// ---------------------------------------------------------------------------
// Launch
// ---------------------------------------------------------------------------
extern "C" void kernel_launch(void* const* d_in, const int* in_sizes, int n_in,
                              void* d_out, int out_size) {
    const float* dense  = (const float*)d_in[0];   // [16384, 512]
    const float* sparse = (const float*)d_in[1];   // [16384, 26, 128]
    const float* Wp     = (const float*)d_in[2];   // [128, 512]
    const float* bp     = (const float*)d_in[3];   // [128]
    const float* Wo     = (const float*)d_in[4];   // [512, 890]
    const float* bo     = (const float*)d_in[5];   // [512]
    float* out = (float*)d_out;                    // [16384, 512]

    pack_wo_kernel<<<OUTD, 256>>>(Wo);
    gemm_proj_kernel<<<dim3(1, BROWS / 128), 256>>>(dense, Wp, bp);
    zflat_kernel<<<BROWS / 2, 64>>>(sparse);
    gemm_out_kernel<<<dim3(OUTD / 128, BROWS / 128), 256>>>(dense, bo, out);
}

// round 8
// speedup vs baseline: 1.5736x; 1.5736x over previous
#include <cuda_runtime.h>
#include <cuda_bf16.h>
#include <cstdint>

// ---------------- problem constants ----------------
#define BROWS 16384
#define DIN   512
#define NSP   26
#define EMB   128
#define OUTD  512
#define NI    27
#define NTRI  378
// packed-A layout (bf16): [0..511]=hi(dense) [512..889]=hi(ztri) [890..895]=0
//                         [896..1407]=lo(dense) [1408..1785]=lo(ztri) [1786..1791]=0
#define KAP   1792
#define ALO   896
#define KWO   2688          // Wo pack: [hi(896) | lo(896) | hi(896)]
#define KWP   1536          // Wp pack: [hi(512) | lo(512) | hi(512)]

// ---------------- device scratch (ONLY referenced from device code!) --------
__device__ __align__(16) __nv_bfloat16 g_apack[BROWS * KAP];
__device__ __align__(16) __nv_bfloat16 g_wopack[OUTD * KWO];
__device__ __align__(16) __nv_bfloat16 g_wppack[EMB * KWP];
__device__ __align__(16) float         g_proj[BROWS * EMB];

// ---------------- helpers ----------------
__device__ __forceinline__ void bf_split(float v, __nv_bfloat16& h, __nv_bfloat16& l) {
    h = __float2bfloat16(v);
    l = __float2bfloat16(v - __bfloat162float(h));
}
__device__ __forceinline__ void mma16816(float* c,
                                         uint32_t a0, uint32_t a1, uint32_t a2, uint32_t a3,
                                         uint32_t b0, uint32_t b1) {
    asm volatile("mma.sync.aligned.m16n8k16.row.col.f32.bf16.bf16.f32 "
                 "{%0,%1,%2,%3}, {%4,%5,%6,%7}, {%8,%9}, {%0,%1,%2,%3};"
                 : "+f"(c[0]), "+f"(c[1]), "+f"(c[2]), "+f"(c[3])
                 : "r"(a0), "r"(a1), "r"(a2), "r"(a3), "r"(b0), "r"(b1));
}

// ---------------------------------------------------------------------------
// pack kernels
// ---------------------------------------------------------------------------
__global__ void pack_dense_kernel(const float* __restrict__ dense) {
    size_t t   = (size_t)blockIdx.x * 256 + threadIdx.x;   // one float4 each
    size_t row = t >> 7;
    int    c4  = (int)(t & 127) * 4;
    float4 v   = *(const float4*)(dense + row * DIN + c4);
    float  vv[4] = {v.x, v.y, v.z, v.w};
    __nv_bfloat16 h[4], l[4];
#pragma unroll
    for (int i = 0; i < 4; i++) bf_split(vv[i], h[i], l[i]);
    __nv_bfloat16* a = g_apack + row * KAP;
    *(__nv_bfloat162*)(a + c4)           = __nv_bfloat162(h[0], h[1]);
    *(__nv_bfloat162*)(a + c4 + 2)       = __nv_bfloat162(h[2], h[3]);
    *(__nv_bfloat162*)(a + ALO + c4)     = __nv_bfloat162(l[0], l[1]);
    *(__nv_bfloat162*)(a + ALO + c4 + 2) = __nv_bfloat162(l[2], l[3]);
}

__global__ void pack_wo_kernel(const float* __restrict__ Wo) {
    int n = blockIdx.x;
    for (int k = threadIdx.x; k < 896; k += 256) {
        float v = (k < 890) ? Wo[(size_t)n * 890 + k] : 0.0f;
        __nv_bfloat16 h, l;
        bf_split(v, h, l);
        __nv_bfloat16* w = g_wopack + (size_t)n * KWO;
        w[k] = h; w[896 + k] = l; w[1792 + k] = h;
    }
}

__global__ void pack_wp_kernel(const float* __restrict__ Wp) {
    int n = blockIdx.x;
    for (int k = threadIdx.x; k < 512; k += 256) {
        float v = Wp[(size_t)n * 512 + k];
        __nv_bfloat16 h, l;
        bf_split(v, h, l);
        __nv_bfloat16* w = g_wppack + (size_t)n * KWP;
        w[k] = h; w[512 + k] = l; w[1024 + k] = h;
    }
}

// ---------------------------------------------------------------------------
// HMMA (mma.sync bf16) tiled GEMM with 3-segment split-K remap.
// MODE 0: proj  -> A=g_apack(K=KAP), W=g_wppack(K=KWP), C=g_proj (ldc=EMB)
// MODE 1: out   -> A=g_apack(K=KAP), W=g_wopack(K=KWO), C=arg    (ldc=OUTD)
// 256 threads = 8 warps, warp tile 64x32 via m16n8k16; BK=32 chunks.
// chunk c: A cols ((c/SC)<2 ? 0 : ALO) + (c%SC)*32, W cols c*32.
// Single smem buffer; chunk c+1 register-prefetched during compute of c.
// ---------------------------------------------------------------------------
#define PADK 40   // bf16 row stride in smem -> 80B, conflict-free LDS pattern

template<int NCH, int SC, int MODE>
__global__ void __launch_bounds__(256, 2)
gemm_mma_kernel(const float* __restrict__ bias, float* __restrict__ C_arg)
{
    __shared__ __align__(16) __nv_bfloat16 As[128 * PADK];
    __shared__ __align__(16) __nv_bfloat16 Bs[128 * PADK];

    // device-code references -> correct generic addresses for __device__ globals
    const __nv_bfloat16* __restrict__ A = g_apack;
    const __nv_bfloat16* __restrict__ W = (MODE == 0) ? g_wppack : g_wopack;
    const int KA  = KAP;
    const int KW  = (MODE == 0) ? KWP : KWO;
    float* __restrict__ C = (MODE == 0) ? g_proj : C_arg;
    const int ldc = (MODE == 0) ? EMB : OUTD;

    const int tid  = threadIdx.x;
    const int wid  = tid >> 5;
    const int lane = tid & 31;
    const int wm   = wid >> 2;     // 0..1 warp-row (64 rows each)
    const int wn   = wid & 3;      // 0..3 warp-col (32 cols each)
    const int m0   = blockIdx.y * 128;
    const int n0   = blockIdx.x * 128;

    float acc[4][4][4];
#pragma unroll
    for (int i = 0; i < 4; i++)
#pragma unroll
        for (int j = 0; j < 4; j++)
#pragma unroll
            for (int q = 0; q < 4; q++) acc[i][j][q] = 0.0f;

    uint4 ra[2], rb[2];

    auto fetch = [&](int c) {
        int seg = c / SC, r = c - seg * SC;
        int ka0 = ((seg < 2) ? 0 : ALO) + r * 32;
        int kw0 = c * 32;
#pragma unroll
        for (int i = 0; i < 2; i++) {
            int idx = tid + i * 256;
            int row = idx >> 2, j = idx & 3;
            ra[i] = *(const uint4*)(A + (size_t)(m0 + row) * KA + ka0 + j * 8);
            rb[i] = *(const uint4*)(W + (size_t)(n0 + row) * KW + kw0 + j * 8);
        }
    };
    auto sts = [&]() {
#pragma unroll
        for (int i = 0; i < 2; i++) {
            int idx = tid + i * 256;
            int row = idx >> 2, j = idx & 3;
            *(uint4*)&As[row * PADK + j * 8] = ra[i];
            *(uint4*)&Bs[row * PADK + j * 8] = rb[i];
        }
    };

    const int lr = lane >> 2;          // 0..7
    const int lc = (lane & 3) * 2;     // 0,2,4,6

    fetch(0);
    for (int c = 0; c < NCH; c++) {
        __syncthreads();               // prior compute done before overwrite
        sts();
        __syncthreads();
        if (c + 1 < NCH) fetch(c + 1); // LDG latency hidden by compute below

#pragma unroll
        for (int ks = 0; ks < 2; ks++) {
            const int kc = ks * 16 + lc;
            uint32_t a[4][4], b[4][2];
#pragma unroll
            for (int mt = 0; mt < 4; mt++) {
                const __nv_bfloat16* p = &As[(wm * 64 + mt * 16 + lr) * PADK + kc];
                a[mt][0] = *(const uint32_t*)p;                    // m,   k
                a[mt][1] = *(const uint32_t*)(p + 8 * PADK);       // m+8, k
                a[mt][2] = *(const uint32_t*)(p + 8);              // m,   k+8
                a[mt][3] = *(const uint32_t*)(p + 8 * PADK + 8);   // m+8, k+8
            }
#pragma unroll
            for (int nt = 0; nt < 4; nt++) {
                const __nv_bfloat16* p = &Bs[(wn * 32 + nt * 8 + lr) * PADK + kc];
                b[nt][0] = *(const uint32_t*)p;                    // n, k
                b[nt][1] = *(const uint32_t*)(p + 8);              // n, k+8
            }
#pragma unroll
            for (int mt = 0; mt < 4; mt++)
#pragma unroll
                for (int nt = 0; nt < 4; nt++)
                    mma16816(acc[mt][nt],
                             a[mt][0], a[mt][1], a[mt][2], a[mt][3],
                             b[nt][0], b[nt][1]);
        }
    }

    // epilogue
    const int r4 = lane >> 2;
    const int c2 = (lane & 3) * 2;
#pragma unroll
    for (int mt = 0; mt < 4; mt++) {
        int mrow = m0 + wm * 64 + mt * 16 + r4;
#pragma unroll
        for (int nt = 0; nt < 4; nt++) {
            int ncol = n0 + wn * 32 + nt * 8 + c2;
            float2 bv = *(const float2*)&bias[ncol];
            float2 o0, o1;
            o0.x = acc[mt][nt][0] + bv.x; o0.y = acc[mt][nt][1] + bv.y;
            o1.x = acc[mt][nt][2] + bv.x; o1.y = acc[mt][nt][3] + bv.y;
            *(float2*)&C[(size_t)mrow * ldc + ncol]       = o0;
            *(float2*)&C[(size_t)(mrow + 8) * ldc + ncol] = o1;
        }
    }
}

// ---------------------------------------------------------------------------
// zflat: per-row Z = T T^T lower-tri, T = [proj_row; sparse_row] (27x128).
// Writes bf16 hi/lo into A_pack cols [512..889]/[1408..1785]; zeroes pads.
// ---------------------------------------------------------------------------
__global__ void __launch_bounds__(64)
zflat_kernel(const float* __restrict__ sparse)
{
    __shared__ __align__(16) float Tt[2][128 * 28];

    const int w    = threadIdx.x >> 5;
    const int lane = threadIdx.x & 31;
    const size_t b = (size_t)blockIdx.x * 2 + w;
    float* T = Tt[w];
    __nv_bfloat16* arow = g_apack + b * KAP;

    // zero pad columns 890..895 (hi) and 1786..1791 (lo)
    if (lane < 6) {
        arow[890 + lane]       = __float2bfloat16(0.0f);
        arow[ALO + 890 + lane] = __float2bfloat16(0.0f);
    }

    {
        const float* src = g_proj + b * 128;
#pragma unroll
        for (int c = 0; c < 4; c++) { int e = lane + 32 * c; T[e * 28 + 0] = src[e]; }
    }
    for (int i = 1; i < NI; i++) {
        const float* src = sparse + (b * NSP + (i - 1)) * 128;
#pragma unroll
        for (int c = 0; c < 4; c++) { int e = lane + 32 * c; T[e * 28 + i] = src[e]; }
    }
    __syncwarp();

    if (lane < 28) {
        int ti = 0, rem = lane;
        while (rem > ti) { rem -= (ti + 1); ti++; }
        int tj = rem;

        float acc[4][4];
#pragma unroll
        for (int r = 0; r < 4; r++)
#pragma unroll
            for (int c = 0; c < 4; c++) acc[r][c] = 0.0f;

#pragma unroll 4
        for (int e = 0; e < 128; e++) {
            float4 av = *(const float4*)&T[e * 28 + 4 * ti];
            float4 bv = *(const float4*)&T[e * 28 + 4 * tj];
            float a[4]  = {av.x, av.y, av.z, av.w};
            float c4[4] = {bv.x, bv.y, bv.z, bv.w};
#pragma unroll
            for (int r = 0; r < 4; r++)
#pragma unroll
                for (int c = 0; c < 4; c++) acc[r][c] += a[r] * c4[c];
        }

#pragma unroll
        for (int r = 0; r < 4; r++) {
            int i = 4 * ti + r;
            if (i < NI) {
#pragma unroll
                for (int c = 0; c < 4; c++) {
                    int j = 4 * tj + c;
                    if (j <= i) {
                        int idx = i * (i + 1) / 2 + j;
                        __nv_bfloat16 h, l;
                        bf_split(acc[r][c], h, l);
                        arow[512 + idx]       = h;
                        arow[ALO + 512 + idx] = l;
                    }
                }
            }
        }
    }
}

// ---------------------------------------------------------------------------
// launch — NOTE: __device__ globals are never referenced here (host code);
// kernels bind them internally via the MODE template parameter.
// ---------------------------------------------------------------------------
extern "C" void kernel_launch(void* const* d_in, const int* in_sizes, int n_in,
                              void* d_out, int out_size) {
    const float* dense  = (const float*)d_in[0];   // [16384, 512]
    const float* sparse = (const float*)d_in[1];   // [16384, 26, 128]
    const float* Wp     = (const float*)d_in[2];   // [128, 512]
    const float* bp     = (const float*)d_in[3];   // [128]
    const float* Wo     = (const float*)d_in[4];   // [512, 890]
    const float* bo     = (const float*)d_in[5];   // [512]
    float* out = (float*)d_out;                    // [16384, 512]

    pack_dense_kernel<<<BROWS * DIN / (4 * 256), 256>>>(dense);
    pack_wp_kernel<<<EMB, 256>>>(Wp);
    pack_wo_kernel<<<OUTD, 256>>>(Wo);

    // proj: g_proj[B,128] = dense @ Wp^T + bp   (K = 3x512 split -> 48 chunks)
    gemm_mma_kernel<48, 16, 0><<<dim3(1, BROWS / 128), 256>>>(bp, nullptr);

    zflat_kernel<<<BROWS / 2, 64>>>(sparse);

    // out: [B,512] = [dense|Ztri] @ Wo^T + bo   (K = 3x896 split -> 84 chunks)
    gemm_mma_kernel<84, 28, 1><<<dim3(OUTD / 128, BROWS / 128), 256>>>(bo, out);
}

// round 9
// speedup vs baseline: 1.5739x; 1.0002x over previous
#include <cuda_runtime.h>
#include <cuda_bf16.h>
#include <cstdint>

// ---------------- problem constants ----------------
#define BROWS 16384
#define DIN   512
#define NSP   26
#define EMB   128
#define OUTD  512
#define NI    27
#define NTRI  378
// packed-A layout (bf16): [0..511]=hi(dense) [512..889]=hi(ztri) [890..895]=0
//                         [896..1407]=lo(dense) [1408..1785]=lo(ztri) [1786..1791]=0
#define KAP   1792
#define ALO   896
#define KWO   2688          // Wo pack: [hi(896) | lo(896) | hi(896)]
#define KWP   1536          // Wp pack: [hi(512) | lo(512) | hi(512)]

// ---------------- device scratch (ONLY referenced from device code!) --------
__device__ __align__(16) __nv_bfloat16 g_apack[BROWS * KAP];
__device__ __align__(16) __nv_bfloat16 g_wopack[OUTD * KWO];
__device__ __align__(16) __nv_bfloat16 g_wppack[EMB * KWP];
__device__ __align__(16) float         g_proj[BROWS * EMB];

// ---------------- helpers ----------------
__device__ __forceinline__ void bf_split(float v, __nv_bfloat16& h, __nv_bfloat16& l) {
    h = __float2bfloat16(v);
    l = __float2bfloat16(v - __bfloat162float(h));
}
__device__ __forceinline__ void mma16816(float* c,
                                         uint32_t a0, uint32_t a1, uint32_t a2, uint32_t a3,
                                         uint32_t b0, uint32_t b1) {
    asm volatile("mma.sync.aligned.m16n8k16.row.col.f32.bf16.bf16.f32 "
                 "{%0,%1,%2,%3}, {%4,%5,%6,%7}, {%8,%9}, {%0,%1,%2,%3};"
                 : "+f"(c[0]), "+f"(c[1]), "+f"(c[2]), "+f"(c[3])
                 : "r"(a0), "r"(a1), "r"(a2), "r"(a3), "r"(b0), "r"(b1));
}

// ---------------------------------------------------------------------------
// pack kernels
// ---------------------------------------------------------------------------
__global__ void pack_dense_kernel(const float* __restrict__ dense) {
    size_t t   = (size_t)blockIdx.x * 256 + threadIdx.x;   // one float4 each
    size_t row = t >> 7;
    int    c4  = (int)(t & 127) * 4;
    float4 v   = *(const float4*)(dense + row * DIN + c4);
    float  vv[4] = {v.x, v.y, v.z, v.w};
    __nv_bfloat16 h[4], l[4];
#pragma unroll
    for (int i = 0; i < 4; i++) bf_split(vv[i], h[i], l[i]);
    __nv_bfloat16* a = g_apack + row * KAP;
    *(__nv_bfloat162*)(a + c4)           = __nv_bfloat162(h[0], h[1]);
    *(__nv_bfloat162*)(a + c4 + 2)       = __nv_bfloat162(h[2], h[3]);
    *(__nv_bfloat162*)(a + ALO + c4)     = __nv_bfloat162(l[0], l[1]);
    *(__nv_bfloat162*)(a + ALO + c4 + 2) = __nv_bfloat162(l[2], l[3]);
}

__global__ void pack_wo_kernel(const float* __restrict__ Wo) {
    int n = blockIdx.x;
    for (int k = threadIdx.x; k < 896; k += 256) {
        float v = (k < 890) ? Wo[(size_t)n * 890 + k] : 0.0f;
        __nv_bfloat16 h, l;
        bf_split(v, h, l);
        __nv_bfloat16* w = g_wopack + (size_t)n * KWO;
        w[k] = h; w[896 + k] = l; w[1792 + k] = h;
    }
}

__global__ void pack_wp_kernel(const float* __restrict__ Wp) {
    int n = blockIdx.x;
    for (int k = threadIdx.x; k < 512; k += 256) {
        float v = Wp[(size_t)n * 512 + k];
        __nv_bfloat16 h, l;
        bf_split(v, h, l);
        __nv_bfloat16* w = g_wppack + (size_t)n * KWP;
        w[k] = h; w[512 + k] = l; w[1024 + k] = h;
    }
}

// ---------------------------------------------------------------------------
// HMMA (mma.sync bf16) tiled GEMM with 3-segment split-K remap.
// MODE 0: proj  -> A=g_apack(K=KAP), W=g_wppack(K=KWP), C=g_proj (ldc=EMB)
// MODE 1: out   -> A=g_apack(K=KAP), W=g_wopack(K=KWO), C=arg    (ldc=OUTD)
// 256 threads = 8 warps, warp tile 64x32 via m16n8k16; BK=32 chunks.
// chunk c: A cols ((c/SC)<2 ? 0 : ALO) + (c%SC)*32, W cols c*32.
// Single smem buffer; chunk c+1 register-prefetched during compute of c.
// ---------------------------------------------------------------------------
#define PADK 40   // bf16 row stride in smem -> 80B, conflict-free LDS pattern

template<int NCH, int SC, int MODE>
__global__ void __launch_bounds__(256, 2)
gemm_mma_kernel(const float* __restrict__ bias, float* __restrict__ C_arg)
{
    __shared__ __align__(16) __nv_bfloat16 As[128 * PADK];
    __shared__ __align__(16) __nv_bfloat16 Bs[128 * PADK];

    // device-code references -> correct generic addresses for __device__ globals
    const __nv_bfloat16* __restrict__ A = g_apack;
    const __nv_bfloat16* __restrict__ W = (MODE == 0) ? g_wppack : g_wopack;
    const int KA  = KAP;
    const int KW  = (MODE == 0) ? KWP : KWO;
    float* __restrict__ C = (MODE == 0) ? g_proj : C_arg;
    const int ldc = (MODE == 0) ? EMB : OUTD;

    const int tid  = threadIdx.x;
    const int wid  = tid >> 5;
    const int lane = tid & 31;
    const int wm   = wid >> 2;     // 0..1 warp-row (64 rows each)
    const int wn   = wid & 3;      // 0..3 warp-col (32 cols each)
    const int m0   = blockIdx.y * 128;
    const int n0   = blockIdx.x * 128;

    float acc[4][4][4];
#pragma unroll
    for (int i = 0; i < 4; i++)
#pragma unroll
        for (int j = 0; j < 4; j++)
#pragma unroll
            for (int q = 0; q < 4; q++) acc[i][j][q] = 0.0f;

    uint4 ra[2], rb[2];

    auto fetch = [&](int c) {
        int seg = c / SC, r = c - seg * SC;
        int ka0 = ((seg < 2) ? 0 : ALO) + r * 32;
        int kw0 = c * 32;
#pragma unroll
        for (int i = 0; i < 2; i++) {
            int idx = tid + i * 256;
            int row = idx >> 2, j = idx & 3;
            ra[i] = *(const uint4*)(A + (size_t)(m0 + row) * KA + ka0 + j * 8);
            rb[i] = *(const uint4*)(W + (size_t)(n0 + row) * KW + kw0 + j * 8);
        }
    };
    auto sts = [&]() {
#pragma unroll
        for (int i = 0; i < 2; i++) {
            int idx = tid + i * 256;
            int row = idx >> 2, j = idx & 3;
            *(uint4*)&As[row * PADK + j * 8] = ra[i];
            *(uint4*)&Bs[row * PADK + j * 8] = rb[i];
        }
    };

    const int lr = lane >> 2;          // 0..7
    const int lc = (lane & 3) * 2;     // 0,2,4,6

    fetch(0);
    for (int c = 0; c < NCH; c++) {
        __syncthreads();               // prior compute done before overwrite
        sts();
        __syncthreads();
        if (c + 1 < NCH) fetch(c + 1); // LDG latency hidden by compute below

#pragma unroll
        for (int ks = 0; ks < 2; ks++) {
            const int kc = ks * 16 + lc;
            uint32_t a[4][4], b[4][2];
#pragma unroll
            for (int mt = 0; mt < 4; mt++) {
                const __nv_bfloat16* p = &As[(wm * 64 + mt * 16 + lr) * PADK + kc];
                a[mt][0] = *(const uint32_t*)p;                    // m,   k
                a[mt][1] = *(const uint32_t*)(p + 8 * PADK);       // m+8, k
                a[mt][2] = *(const uint32_t*)(p + 8);              // m,   k+8
                a[mt][3] = *(const uint32_t*)(p + 8 * PADK + 8);   // m+8, k+8
            }
#pragma unroll
            for (int nt = 0; nt < 4; nt++) {
                const __nv_bfloat16* p = &Bs[(wn * 32 + nt * 8 + lr) * PADK + kc];
                b[nt][0] = *(const uint32_t*)p;                    // n, k
                b[nt][1] = *(const uint32_t*)(p + 8);              // n, k+8
            }
#pragma unroll
            for (int mt = 0; mt < 4; mt++)
#pragma unroll
                for (int nt = 0; nt < 4; nt++)
                    mma16816(acc[mt][nt],
                             a[mt][0], a[mt][1], a[mt][2], a[mt][3],
                             b[nt][0], b[nt][1]);
        }
    }

    // epilogue
    const int r4 = lane >> 2;
    const int c2 = (lane & 3) * 2;
#pragma unroll
    for (int mt = 0; mt < 4; mt++) {
        int mrow = m0 + wm * 64 + mt * 16 + r4;
#pragma unroll
        for (int nt = 0; nt < 4; nt++) {
            int ncol = n0 + wn * 32 + nt * 8 + c2;
            float2 bv = *(const float2*)&bias[ncol];
            float2 o0, o1;
            o0.x = acc[mt][nt][0] + bv.x; o0.y = acc[mt][nt][1] + bv.y;
            o1.x = acc[mt][nt][2] + bv.x; o1.y = acc[mt][nt][3] + bv.y;
            *(float2*)&C[(size_t)mrow * ldc + ncol]       = o0;
            *(float2*)&C[(size_t)(mrow + 8) * ldc + ncol] = o1;
        }
    }
}

// ---------------------------------------------------------------------------
// zflat: per-row Z = T T^T lower-tri, T = [proj_row; sparse_row] (27x128).
// Writes bf16 hi/lo into A_pack cols [512..889]/[1408..1785]; zeroes pads.
// ---------------------------------------------------------------------------
__global__ void __launch_bounds__(64)
zflat_kernel(const float* __restrict__ sparse)
{
    __shared__ __align__(16) float Tt[2][128 * 28];

    const int w    = threadIdx.x >> 5;
    const int lane = threadIdx.x & 31;
    const size_t b = (size_t)blockIdx.x * 2 + w;
    float* T = Tt[w];
    __nv_bfloat16* arow = g_apack + b * KAP;

    // zero pad columns 890..895 (hi) and 1786..1791 (lo)
    if (lane < 6) {
        arow[890 + lane]       = __float2bfloat16(0.0f);
        arow[ALO + 890 + lane] = __float2bfloat16(0.0f);
    }

    {
        const float* src = g_proj + b * 128;
#pragma unroll
        for (int c = 0; c < 4; c++) { int e = lane + 32 * c; T[e * 28 + 0] = src[e]; }
    }
    for (int i = 1; i < NI; i++) {
        const float* src = sparse + (b * NSP + (i - 1)) * 128;
#pragma unroll
        for (int c = 0; c < 4; c++) { int e = lane + 32 * c; T[e * 28 + i] = src[e]; }
    }
    __syncwarp();

    if (lane < 28) {
        int ti = 0, rem = lane;
        while (rem > ti) { rem -= (ti + 1); ti++; }
        int tj = rem;

        float acc[4][4];
#pragma unroll
        for (int r = 0; r < 4; r++)
#pragma unroll
            for (int c = 0; c < 4; c++) acc[r][c] = 0.0f;

#pragma unroll 4
        for (int e = 0; e < 128; e++) {
            float4 av = *(const float4*)&T[e * 28 + 4 * ti];
            float4 bv = *(const float4*)&T[e * 28 + 4 * tj];
            float a[4]  = {av.x, av.y, av.z, av.w};
            float c4[4] = {bv.x, bv.y, bv.z, bv.w};
#pragma unroll
            for (int r = 0; r < 4; r++)
#pragma unroll
                for (int c = 0; c < 4; c++) acc[r][c] += a[r] * c4[c];
        }

#pragma unroll
        for (int r = 0; r < 4; r++) {
            int i = 4 * ti + r;
            if (i < NI) {
#pragma unroll
                for (int c = 0; c < 4; c++) {
                    int j = 4 * tj + c;
                    if (j <= i) {
                        int idx = i * (i + 1) / 2 + j;
                        __nv_bfloat16 h, l;
                        bf_split(acc[r][c], h, l);
                        arow[512 + idx]       = h;
                        arow[ALO + 512 + idx] = l;
                    }
                }
            }
        }
    }
}

// ---------------------------------------------------------------------------
// launch — NOTE: __device__ globals are never referenced here (host code);
// kernels bind them internally via the MODE template parameter.
// ---------------------------------------------------------------------------
extern "C" void kernel_launch(void* const* d_in, const int* in_sizes, int n_in,
                              void* d_out, int out_size) {
    const float* dense  = (const float*)d_in[0];   // [16384, 512]
    const float* sparse = (const float*)d_in[1];   // [16384, 26, 128]
    const float* Wp     = (const float*)d_in[2];   // [128, 512]
    const float* bp     = (const float*)d_in[3];   // [128]
    const float* Wo     = (const float*)d_in[4];   // [512, 890]
    const float* bo     = (const float*)d_in[5];   // [512]
    float* out = (float*)d_out;                    // [16384, 512]

    pack_dense_kernel<<<BROWS * DIN / (4 * 256), 256>>>(dense);
    pack_wp_kernel<<<EMB, 256>>>(Wp);
    pack_wo_kernel<<<OUTD, 256>>>(Wo);

    // proj: g_proj[B,128] = dense @ Wp^T + bp   (K = 3x512 split -> 48 chunks)
    gemm_mma_kernel<48, 16, 0><<<dim3(1, BROWS / 128), 256>>>(bp, nullptr);

    zflat_kernel<<<BROWS / 2, 64>>>(sparse);

    // out: [B,512] = [dense|Ztri] @ Wo^T + bo   (K = 3x896 split -> 84 chunks)
    gemm_mma_kernel<84, 28, 1><<<dim3(OUTD / 128, BROWS / 128), 256>>>(bo, out);
}

// round 10
// speedup vs baseline: 1.6123x; 1.0244x over previous
#include <cuda_runtime.h>
#include <cuda_bf16.h>
#include <cstdint>

// ---------------- problem constants ----------------
#define BROWS 16384
#define DIN   512
#define NSP   26
#define EMB   128
#define OUTD  512
#define NI    27
#define NTRI  378
// packed-A layout (bf16): [0..511]=hi(dense) [512..889]=hi(ztri) [890..895]=0
//                         [896..1407]=lo(dense) [1408..1785]=lo(ztri) [1786..1791]=0
#define KAP   1792
#define ALO   896
#define KWO   2688          // Wo pack: [hi(896) | lo(896) | hi(896)]
#define KWP   1536          // Wp pack: [hi(512) | lo(512) | hi(512)]

// ---------------- device scratch (ONLY referenced from device code!) --------
__device__ __align__(16) __nv_bfloat16 g_apack[BROWS * KAP];
__device__ __align__(16) __nv_bfloat16 g_wopack[OUTD * KWO];
__device__ __align__(16) __nv_bfloat16 g_wppack[EMB * KWP];
__device__ __align__(16) float         g_proj[BROWS * EMB];

// ---------------- helpers ----------------
__device__ __forceinline__ void bf_split(float v, __nv_bfloat16& h, __nv_bfloat16& l) {
    h = __float2bfloat16(v);
    l = __float2bfloat16(v - __bfloat162float(h));
}
__device__ __forceinline__ uint32_t smem_u32(const void* p) {
    uint32_t a;
    asm("{ .reg .u64 t; cvta.to.shared.u64 t, %1; cvt.u32.u64 %0, t; }" : "=r"(a) : "l"(p));
    return a;
}
__device__ __forceinline__ void cp_async16(uint32_t s, const void* g) {
    asm volatile("cp.async.cg.shared.global [%0], [%1], 16;" :: "r"(s), "l"(g) : "memory");
}
__device__ __forceinline__ void ldsm_x4(uint32_t& r0, uint32_t& r1, uint32_t& r2, uint32_t& r3,
                                        uint32_t addr) {
    asm volatile("ldmatrix.sync.aligned.m8n8.x4.shared.b16 {%0,%1,%2,%3}, [%4];"
                 : "=r"(r0), "=r"(r1), "=r"(r2), "=r"(r3) : "r"(addr));
}
__device__ __forceinline__ void mma16816(float* c,
                                         uint32_t a0, uint32_t a1, uint32_t a2, uint32_t a3,
                                         uint32_t b0, uint32_t b1) {
    asm volatile("mma.sync.aligned.m16n8k16.row.col.f32.bf16.bf16.f32 "
                 "{%0,%1,%2,%3}, {%4,%5,%6,%7}, {%8,%9}, {%0,%1,%2,%3};"
                 : "+f"(c[0]), "+f"(c[1]), "+f"(c[2]), "+f"(c[3])
                 : "r"(a0), "r"(a1), "r"(a2), "r"(a3), "r"(b0), "r"(b1));
}

// ---------------------------------------------------------------------------
// pack kernels
// ---------------------------------------------------------------------------
__global__ void pack_dense_kernel(const float* __restrict__ dense) {
    size_t t   = (size_t)blockIdx.x * 256 + threadIdx.x;   // one float4 each
    size_t row = t >> 7;
    int    c4  = (int)(t & 127) * 4;
    float4 v   = *(const float4*)(dense + row * DIN + c4);
    float  vv[4] = {v.x, v.y, v.z, v.w};
    __nv_bfloat16 h[4], l[4];
#pragma unroll
    for (int i = 0; i < 4; i++) bf_split(vv[i], h[i], l[i]);
    __nv_bfloat16* a = g_apack + row * KAP;
    *(__nv_bfloat162*)(a + c4)           = __nv_bfloat162(h[0], h[1]);
    *(__nv_bfloat162*)(a + c4 + 2)       = __nv_bfloat162(h[2], h[3]);
    *(__nv_bfloat162*)(a + ALO + c4)     = __nv_bfloat162(l[0], l[1]);
    *(__nv_bfloat162*)(a + ALO + c4 + 2) = __nv_bfloat162(l[2], l[3]);
}

__global__ void pack_wo_kernel(const float* __restrict__ Wo) {
    int n = blockIdx.x;
    for (int k = threadIdx.x; k < 896; k += 256) {
        float v = (k < 890) ? Wo[(size_t)n * 890 + k] : 0.0f;
        __nv_bfloat16 h, l;
        bf_split(v, h, l);
        __nv_bfloat16* w = g_wopack + (size_t)n * KWO;
        w[k] = h; w[896 + k] = l; w[1792 + k] = h;
    }
}

__global__ void pack_wp_kernel(const float* __restrict__ Wp) {
    int n = blockIdx.x;
    for (int k = threadIdx.x; k < 512; k += 256) {
        float v = Wp[(size_t)n * 512 + k];
        __nv_bfloat16 h, l;
        bf_split(v, h, l);
        __nv_bfloat16* w = g_wppack + (size_t)n * KWP;
        w[k] = h; w[512 + k] = l; w[1024 + k] = h;
    }
}

// ---------------------------------------------------------------------------
// HMMA (mma.sync bf16) tiled GEMM with 3-segment split-K remap.
// MODE 0: proj  -> A=g_apack(K=KAP), W=g_wppack(K=KWP), C=g_proj (ldc=EMB)
// MODE 1: out   -> A=g_apack(K=KAP), W=g_wopack(K=KWO), C=arg    (ldc=OUTD)
// 256 threads = 8 warps, warp tile 64x32 via m16n8k16; BK=32 chunks.
// chunk c: A cols ((c/SC)<2 ? 0 : ALO) + (c%SC)*32, W cols c*32.
// cp.async double-buffered; ldmatrix.x4 fragment loads.
// ---------------------------------------------------------------------------
#define PADK 40   // bf16 row stride in smem -> 80B = 20-bank shift, conflict-free

template<int NCH, int SC, int MODE>
__global__ void __launch_bounds__(256, 2)
gemm_mma_kernel(const float* __restrict__ bias, float* __restrict__ C_arg)
{
    __shared__ __align__(16) __nv_bfloat16 As[2][128 * PADK];
    __shared__ __align__(16) __nv_bfloat16 Bs[2][128 * PADK];

    const __nv_bfloat16* __restrict__ A = g_apack;
    const __nv_bfloat16* __restrict__ W = (MODE == 0) ? g_wppack : g_wopack;
    const int KA  = KAP;
    const int KW  = (MODE == 0) ? KWP : KWO;
    float* __restrict__ C = (MODE == 0) ? g_proj : C_arg;
    const int ldc = (MODE == 0) ? EMB : OUTD;

    const int tid  = threadIdx.x;
    const int wid  = tid >> 5;
    const int lane = tid & 31;
    const int wm   = wid >> 2;     // 0..1 warp-row (64 rows each)
    const int wn   = wid & 3;      // 0..3 warp-col (32 cols each)
    const int m0   = blockIdx.y * 128;
    const int n0   = blockIdx.x * 128;

    float acc[4][4][4];
#pragma unroll
    for (int i = 0; i < 4; i++)
#pragma unroll
        for (int j = 0; j < 4; j++)
#pragma unroll
            for (int q = 0; q < 4; q++) acc[i][j][q] = 0.0f;

    auto load = [&](int c, int buf) {
        int seg = c / SC, r = c - seg * SC;
        int ka0 = ((seg < 2) ? 0 : ALO) + r * 32;
        int kw0 = c * 32;
#pragma unroll
        for (int i = 0; i < 2; i++) {
            int idx = tid + i * 256;           // 512 uint4 tasks each for A and B
            int row = idx >> 2, j = idx & 3;
            cp_async16(smem_u32(&As[buf][row * PADK + j * 8]),
                       A + (size_t)(m0 + row) * KA + ka0 + j * 8);
            cp_async16(smem_u32(&Bs[buf][row * PADK + j * 8]),
                       W + (size_t)(n0 + row) * KW + kw0 + j * 8);
        }
    };

    auto compute = [&](int buf) {
#pragma unroll
        for (int ks = 0; ks < 2; ks++) {
            uint32_t a[4][4], b[2][4];
            // A: rows wm*64+mt*16+(lane&15), col ks*16+(lane>>4)*8
            //   -> quads: (m,k),(m+8,k),(m,k+8),(m+8,k+8) = mma a0..a3
#pragma unroll
            for (int mt = 0; mt < 4; mt++) {
                uint32_t addr = smem_u32(
                    &As[buf][(wm * 64 + mt * 16 + (lane & 15)) * PADK +
                             ks * 16 + (lane >> 4) * 8]);
                ldsm_x4(a[mt][0], a[mt][1], a[mt][2], a[mt][3], addr);
            }
            // B: rows wn*32+nt2*16+((lane>>4)&1)*8+(lane&7), col ks*16+((lane>>3)&1)*8
            //   -> quads: (n,k),(n,k+8),(n+8,k),(n+8,k+8)
#pragma unroll
            for (int nt2 = 0; nt2 < 2; nt2++) {
                uint32_t addr = smem_u32(
                    &Bs[buf][(wn * 32 + nt2 * 16 + ((lane >> 4) & 1) * 8 + (lane & 7)) * PADK +
                             ks * 16 + ((lane >> 3) & 1) * 8]);
                ldsm_x4(b[nt2][0], b[nt2][1], b[nt2][2], b[nt2][3], addr);
            }
#pragma unroll
            for (int mt = 0; mt < 4; mt++)
#pragma unroll
                for (int nt = 0; nt < 4; nt++) {
                    int nt2 = nt >> 1, hb = (nt & 1) * 2;   // nt even -> (n,k),(n,k+8); odd -> n+8
                    mma16816(acc[mt][nt],
                             a[mt][0], a[mt][1], a[mt][2], a[mt][3],
                             b[nt2][hb], b[nt2][hb + 1]);
                }
        }
    };

    load(0, 0);
    asm volatile("cp.async.commit_group;" ::: "memory");

    for (int c = 0; c < NCH; c++) {
        if (c + 1 < NCH) {
            load(c + 1, (c + 1) & 1);
            asm volatile("cp.async.commit_group;" ::: "memory");
            asm volatile("cp.async.wait_group 1;" ::: "memory");
        } else {
            asm volatile("cp.async.wait_group 0;" ::: "memory");
        }
        __syncthreads();
        compute(c & 1);
        __syncthreads();
    }

    // epilogue
    const int r4 = lane >> 2;
    const int c2 = (lane & 3) * 2;
#pragma unroll
    for (int mt = 0; mt < 4; mt++) {
        int mrow = m0 + wm * 64 + mt * 16 + r4;
#pragma unroll
        for (int nt = 0; nt < 4; nt++) {
            int ncol = n0 + wn * 32 + nt * 8 + c2;
            float2 bv = *(const float2*)&bias[ncol];
            float2 o0, o1;
            o0.x = acc[mt][nt][0] + bv.x; o0.y = acc[mt][nt][1] + bv.y;
            o1.x = acc[mt][nt][2] + bv.x; o1.y = acc[mt][nt][3] + bv.y;
            *(float2*)&C[(size_t)mrow * ldc + ncol]       = o0;
            *(float2*)&C[(size_t)(mrow + 8) * ldc + ncol] = o1;
        }
    }
}

// ---------------------------------------------------------------------------
// zflat: per-row Z = T T^T lower-tri, T = [proj_row; sparse_row] (27x128).
// Writes bf16 hi/lo into A_pack cols [512..889]/[1408..1785]; zeroes pads.
// ---------------------------------------------------------------------------
__global__ void __launch_bounds__(64)
zflat_kernel(const float* __restrict__ sparse)
{
    __shared__ __align__(16) float Tt[2][128 * 28];

    const int w    = threadIdx.x >> 5;
    const int lane = threadIdx.x & 31;
    const size_t b = (size_t)blockIdx.x * 2 + w;
    float* T = Tt[w];
    __nv_bfloat16* arow = g_apack + b * KAP;

    if (lane < 6) {
        arow[890 + lane]       = __float2bfloat16(0.0f);
        arow[ALO + 890 + lane] = __float2bfloat16(0.0f);
    }

    {
        const float* src = g_proj + b * 128;
#pragma unroll
        for (int c = 0; c < 4; c++) { int e = lane + 32 * c; T[e * 28 + 0] = src[e]; }
    }
    for (int i = 1; i < NI; i++) {
        const float* src = sparse + (b * NSP + (i - 1)) * 128;
#pragma unroll
        for (int c = 0; c < 4; c++) { int e = lane + 32 * c; T[e * 28 + i] = src[e]; }
    }
    __syncwarp();

    if (lane < 28) {
        int ti = 0, rem = lane;
        while (rem > ti) { rem -= (ti + 1); ti++; }
        int tj = rem;

        float acc[4][4];
#pragma unroll
        for (int r = 0; r < 4; r++)
#pragma unroll
            for (int c = 0; c < 4; c++) acc[r][c] = 0.0f;

#pragma unroll 4
        for (int e = 0; e < 128; e++) {
            float4 av = *(const float4*)&T[e * 28 + 4 * ti];
            float4 bv = *(const float4*)&T[e * 28 + 4 * tj];
            float a[4]  = {av.x, av.y, av.z, av.w};
            float c4[4] = {bv.x, bv.y, bv.z, bv.w};
#pragma unroll
            for (int r = 0; r < 4; r++)
#pragma unroll
                for (int c = 0; c < 4; c++) acc[r][c] += a[r] * c4[c];
        }

#pragma unroll
        for (int r = 0; r < 4; r++) {
            int i = 4 * ti + r;
            if (i < NI) {
#pragma unroll
                for (int c = 0; c < 4; c++) {
                    int j = 4 * tj + c;
                    if (j <= i) {
                        int idx = i * (i + 1) / 2 + j;
                        __nv_bfloat16 h, l;
                        bf_split(acc[r][c], h, l);
                        arow[512 + idx]       = h;
                        arow[ALO + 512 + idx] = l;
                    }
                }
            }
        }
    }
}

// ---------------------------------------------------------------------------
// launch — __device__ globals never referenced from host code (MODE binding).
// ---------------------------------------------------------------------------
extern "C" void kernel_launch(void* const* d_in, const int* in_sizes, int n_in,
                              void* d_out, int out_size) {
    const float* dense  = (const float*)d_in[0];   // [16384, 512]
    const float* sparse = (const float*)d_in[1];   // [16384, 26, 128]
    const float* Wp     = (const float*)d_in[2];   // [128, 512]
    const float* bp     = (const float*)d_in[3];   // [128]
    const float* Wo     = (const float*)d_in[4];   // [512, 890]
    const float* bo     = (const float*)d_in[5];   // [512]
    float* out = (float*)d_out;                    // [16384, 512]

    pack_dense_kernel<<<BROWS * DIN / (4 * 256), 256>>>(dense);
    pack_wp_kernel<<<EMB, 256>>>(Wp);
    pack_wo_kernel<<<OUTD, 256>>>(Wo);

    // proj: g_proj[B,128] = dense @ Wp^T + bp   (K = 3x512 split -> 48 chunks)
    gemm_mma_kernel<48, 16, 0><<<dim3(1, BROWS / 128), 256>>>(bp, nullptr);

    zflat_kernel<<<BROWS / 2, 64>>>(sparse);

    // out: [B,512] = [dense|Ztri] @ Wo^T + bo   (K = 3x896 split -> 84 chunks)
    gemm_mma_kernel<84, 28, 1><<<dim3(OUTD / 128, BROWS / 128), 256>>>(bo, out);
}